// round 10
// baseline (speedup 1.0000x reference)
#include <cuda_runtime.h>
#include <cuda_bf16.h>
#include <cstdint>

// Shapes (fixed by the problem)
#define L_DIM 4
#define B_DIM 8
#define C_DIM 256
#define HW    4096                      // 64*64
#define LBC   (L_DIM * B_DIM * C_DIM)   // 8192
#define NBLOCKS 1184                    // 148 SMs x 8 resident blocks
#define PLANES_PER_PAIR 2048            // 2 batches x L x C

// Scratch in device globals (no allocations allowed)
__device__ float g_gap[LBC];
__device__ unsigned g_count = 0;
__device__ volatile unsigned g_sense = 0;

// Grid-wide sense-reversing barrier. Safe: all NBLOCKS CTAs are resident
// (launch_bounds guarantees 8 blocks/SM x 148 SMs = 1184 = gridDim).
__device__ __forceinline__ void grid_barrier() {
    __syncthreads();
    if (threadIdx.x == 0) {
        __threadfence();                         // publish our g_gap writes
        unsigned s = g_sense;
        unsigned arr = atomicAdd(&g_count, 1u);
        if (arr == (unsigned)(gridDim.x - 1)) {
            g_count = 0;
            __threadfence();
            g_sense = s + 1;                     // release all waiters
        } else {
            while (g_sense == s) { __nanosleep(64); }
        }
        __threadfence();                         // acquire others' writes
    }
    __syncthreads();
}

// ---------------------------------------------------------------------------
// Single persistent kernel, software-pipelined over batch pairs:
//   stage k: GAP-reduce batch pair k (input lands in L2)
//            + scale batch pair k-1 (input re-read hits L2 from stage k-1)
// 5 stages, 5 grid barriers. DRAM traffic: 134 MB read + 134 MB write;
// the 134 MB re-read is served from L2.
// ---------------------------------------------------------------------------
__global__ __launch_bounds__(128, 8)
void sffm_persistent(const float* __restrict__ in,
                     const float* __restrict__ Wlin,
                     float* __restrict__ out) {
    const int t = threadIdx.x;
    __shared__ float shA[4];
    __shared__ float shB[4][4];

    for (int stage = 0; stage < 5; ++stage) {
        // ---------------- Phase A: GAP-reduce batch pair `stage` ----------
        if (stage < 4) {
            for (int pl = blockIdx.x; pl < PLANES_PER_PAIR; pl += gridDim.x) {
                const int b  = stage * 2 + (pl >> 10);
                const int l  = (pl >> 8) & 3;
                const int c  = pl & 255;
                const int bc = (l * B_DIM + b) * C_DIM + c;
                const float4* p = reinterpret_cast<const float4*>(in) + (size_t)bc * (HW / 4);

                float s = 0.0f;
#pragma unroll
                for (int k = 0; k < 8; ++k) {
                    float4 v = p[t + k * 128];
                    s += (v.x + v.y) + (v.z + v.w);
                }
#pragma unroll
                for (int o = 16; o > 0; o >>= 1)
                    s += __shfl_xor_sync(0xffffffffu, s, o);
                if ((t & 31) == 0) shA[t >> 5] = s;
                __syncthreads();
                if (t == 0)
                    g_gap[bc] = (shA[0] + shA[1] + shA[2] + shA[3]) * (1.0f / (float)HW);
                __syncthreads();
            }
        }

        grid_barrier();   // gap of pair `stage` globally visible

        // ---------------- Phase B: scale batch pair `stage-1` -------------
        if (stage > 0) {
            for (int pl = blockIdx.x; pl < PLANES_PER_PAIR; pl += gridDim.x) {
                const int b  = (stage - 1) * 2 + (pl >> 10);
                const int l  = (pl >> 8) & 3;
                const int c  = pl & 255;
                const int bc = (l * B_DIM + b) * C_DIM + c;
                const float4* p = reinterpret_cast<const float4*>(in) + (size_t)bc * (HW / 4);
                float4* o = reinterpret_cast<float4*>(out) + (size_t)bc * (HW / 4);

                // Front-batch the 8 plane loads (should be L2 hits).
                float4 v0 = p[t + 0 * 128];
                float4 v1 = p[t + 1 * 128];
                float4 v2 = p[t + 2 * 128];
                float4 v3 = p[t + 3 * 128];
                float4 v4 = p[t + 4 * 128];
                float4 v5 = p[t + 5 * 128];
                float4 v6 = p[t + 6 * 128];
                float4 v7 = p[t + 7 * 128];

                // attn scalar (redundant per block), hidden under the loads.
                const float* wr = Wlin + (size_t)c * C_DIM;
                float pa0 = 0.f, pa1 = 0.f, pa2 = 0.f, pa3 = 0.f;
#pragma unroll
                for (int j = 0; j < 2; ++j) {
                    const int c2 = t + 128 * j;
                    const float w = wr[c2];
                    pa0 = fmaf(w, g_gap[(0 * B_DIM + b) * C_DIM + c2], pa0);
                    pa1 = fmaf(w, g_gap[(1 * B_DIM + b) * C_DIM + c2], pa1);
                    pa2 = fmaf(w, g_gap[(2 * B_DIM + b) * C_DIM + c2], pa2);
                    pa3 = fmaf(w, g_gap[(3 * B_DIM + b) * C_DIM + c2], pa3);
                }
#pragma unroll
                for (int off = 16; off > 0; off >>= 1) {
                    pa0 += __shfl_xor_sync(0xffffffffu, pa0, off);
                    pa1 += __shfl_xor_sync(0xffffffffu, pa1, off);
                    pa2 += __shfl_xor_sync(0xffffffffu, pa2, off);
                    pa3 += __shfl_xor_sync(0xffffffffu, pa3, off);
                }
                const int warp = t >> 5;
                if ((t & 31) == 0) {
                    shB[warp][0] = pa0; shB[warp][1] = pa1;
                    shB[warp][2] = pa2; shB[warp][3] = pa3;
                }
                __syncthreads();
                const float s0 = shB[0][0] + shB[1][0] + shB[2][0] + shB[3][0];
                const float s1 = shB[0][1] + shB[1][1] + shB[2][1] + shB[3][1];
                const float s2 = shB[0][2] + shB[1][2] + shB[2][2] + shB[3][2];
                const float s3 = shB[0][3] + shB[1][3] + shB[2][3] + shB[3][3];
                __syncthreads();

                const float m  = fmaxf(fmaxf(s0, s1), fmaxf(s2, s3));
                const float e0 = __expf(s0 - m), e1 = __expf(s1 - m);
                const float e2 = __expf(s2 - m), e3 = __expf(s3 - m);
                const float inv = 1.0f / (e0 + e1 + e2 + e3);
                const float el  = (l == 0) ? e0 : (l == 1) ? e1 : (l == 2) ? e2 : e3;
                const float a   = el * inv;

                v0.x *= a; v0.y *= a; v0.z *= a; v0.w *= a;
                v1.x *= a; v1.y *= a; v1.z *= a; v1.w *= a;
                v2.x *= a; v2.y *= a; v2.z *= a; v2.w *= a;
                v3.x *= a; v3.y *= a; v3.z *= a; v3.w *= a;
                v4.x *= a; v4.y *= a; v4.z *= a; v4.w *= a;
                v5.x *= a; v5.y *= a; v5.z *= a; v5.w *= a;
                v6.x *= a; v6.y *= a; v6.z *= a; v6.w *= a;
                v7.x *= a; v7.y *= a; v7.z *= a; v7.w *= a;

                o[t + 0 * 128] = v0;
                o[t + 1 * 128] = v1;
                o[t + 2 * 128] = v2;
                o[t + 3 * 128] = v3;
                o[t + 4 * 128] = v4;
                o[t + 5 * 128] = v5;
                o[t + 6 * 128] = v6;
                o[t + 7 * 128] = v7;
            }
        }
    }
}

extern "C" void kernel_launch(void* const* d_in, const int* in_sizes, int n_in,
                              void* d_out, int out_size) {
    const float* inputs = (const float*)d_in[0];   // [L,B,C,H,W] f32
    const float* Wlin   = (const float*)d_in[1];   // [C,C] f32
    float* out = (float*)d_out;

    sffm_persistent<<<NBLOCKS, 128>>>(inputs, Wlin, out);
}